// round 9
// baseline (speedup 1.0000x reference)
#include <cuda_runtime.h>
#include <math.h>

#define N_POINTS 16384
#define N_PAIRS  65536

#define T_SUPER  16
#define N_SUPER  136                         // upper-triangle 1024x1024 supertiles
#define SUBS_PER_SUPER 8                     // 2 i-halves (512) x 4 j-quarters (256)
#define HEAVY_BLOCKS (N_SUPER * SUBS_PER_SUPER)  // 1088
#define PAIR_BLOCKS  64
#define NBLOCKS  (HEAVY_BLOCKS + PAIR_BLOCKS)    // 1152
#define JTILE 256

typedef unsigned int u32;

// ---- device scratch (no allocation allowed) ----------------------------------
__device__ float g_part_p[HEAVY_BLOCKS];
__device__ float g_kld_p[PAIR_BLOCKS];
__device__ float g_pair_p[PAIR_BLOCKS];
__device__ float g_pij_p[PAIR_BLOCKS];
__device__ unsigned int g_ticket = 0;

__device__ __forceinline__ float rcp_fast(float x) {
    float r; asm("rcp.approx.f32 %0, %1;" : "=f"(r) : "f"(x)); return r;
}

// ---- reductions ----------------------------------------------------------------
__device__ __forceinline__ float warp_reduce(float v) {
    #pragma unroll
    for (int o = 16; o > 0; o >>= 1) v += __shfl_xor_sync(0xffffffffu, v, o);
    return v;
}
__device__ __forceinline__ float block_reduce(float v, float* smem) {
    v = warp_reduce(v);
    int lane = threadIdx.x & 31, wid = threadIdx.x >> 5;
    if (lane == 0) smem[wid] = v;
    __syncthreads();
    v = (threadIdx.x < 8) ? smem[threadIdx.x] : 0.0f;
    if (wid == 0) {
        #pragma unroll
        for (int o = 4; o > 0; o >>= 1) v += __shfl_xor_sync(0xffffffffu, v, o);
    }
    return v;  // valid in thread 0
}

// ---- reparam helper: x = eps*exp(0.5*lv) + mu ----------------------------------
__device__ __forceinline__ float2 reparam_pt(const float* __restrict__ mu,
                                             const float* __restrict__ lv,
                                             const float* __restrict__ eps,
                                             int idx) {
    float2 m = ((const float2*)mu)[idx];
    float2 l = ((const float2*)lv)[idx];
    float2 e = ((const float2*)eps)[idx];
    float2 x;
    x.x = fmaf(e.x, __expf(0.5f * l.x), m.x);
    x.y = fmaf(e.y, __expf(0.5f * l.y), m.y);
    return x;
}

// ---- single fused kernel --------------------------------------------------------
__global__ __launch_bounds__(256, 6)
void k_main(const float* __restrict__ pij,
            const int*   __restrict__ ii,
            const int*   __restrict__ jj,
            const float* __restrict__ mu,
            const float* __restrict__ lv,
            const float* __restrict__ epsf,
            const float* __restrict__ epsi,
            const float* __restrict__ epsj,
            float* __restrict__ out) {
    __shared__ __align__(16) float4 s_j[JTILE];   // per j: (cx=-2xjx, cy=-2xjy, b=1+|xj|^2, 0)
    __shared__ float  sred[8];
    __shared__ float  sred1[8];
    __shared__ double sdd[256];
    __shared__ unsigned int s_last;

    const int bid = blockIdx.x;
    const int tid = threadIdx.x;

    if (bid < HEAVY_BLOCKS) {
        // -------- heavy path: supertile s, sub-block (i-half, j-quarter) --------
        int s = bid >> 3;
        int sub = bid & 7;
        int a = 0, rem = s;
        while (rem >= T_SUPER - a) { rem -= T_SUPER - a; a++; }
        int b = a + rem;
        int i0 = a * 1024 + (sub >> 2) * 512;
        int j0 = b * 1024 + (sub & 3)  * JTILE;
        float wt = (a == b) ? 1.0f : 2.0f;

        // build j-tile in shared (reparam on the fly)
        {
            float2 xj = reparam_pt(mu, lv, epsf, j0 + tid);
            s_j[tid] = make_float4(-2.0f * xj.x, -2.0f * xj.y,
                                   fmaf(xj.x, xj.x, fmaf(xj.y, xj.y, 1.0f)), 0.0f);
        }

        // two i-chains per thread (512 i per CTA)
        float2 xa = reparam_pt(mu, lv, epsf, i0 + tid);
        float2 xb = reparam_pt(mu, lv, epsf, i0 + 256 + tid);
        float ha = fmaf(xa.x, xa.x, xa.y * xa.y);   // |xi|^2
        float hb = fmaf(xb.x, xb.x, xb.y * xb.y);

        // separate accumulators per path per chain (relax dep chains)
        float accNa = 0.0f, accNb = 0.0f;   // newton path
        float accMa = 0.0f, accMb = 0.0f;   // mufu path

        __syncthreads();

        #pragma unroll 8
        for (int it = 0; it < JTILE / 2; it++) {
            float4 j0v = s_j[2 * it];       // LDS.128 broadcast
            float4 j1v = s_j[2 * it + 1];

            // j0: magic + 1 Newton on the fma pipe
            float d0a = fmaf(j0v.x, xa.x, fmaf(j0v.y, xa.y, j0v.z + ha));
            float y0a = __uint_as_float(0x7EF127EAu - __float_as_uint(d0a));
            accNa = fmaf(y0a, fmaf(-d0a, y0a, 2.0f), accNa);

            float d0b = fmaf(j0v.x, xb.x, fmaf(j0v.y, xb.y, j0v.z + hb));
            float y0b = __uint_as_float(0x7EF127EAu - __float_as_uint(d0b));
            accNb = fmaf(y0b, fmaf(-d0b, y0b, 2.0f), accNb);

            // j1: MUFU.RCP path
            float d1a = fmaf(j1v.x, xa.x, fmaf(j1v.y, xa.y, j1v.z + ha));
            accMa += rcp_fast(d1a);

            float d1b = fmaf(j1v.x, xb.x, fmaf(j1v.y, xb.y, j1v.z + hb));
            accMb += rcp_fast(d1b);
        }

        float sres = block_reduce((accNa + accNb) + (accMa + accMb), sred);
        if (tid == 0) g_part_p[bid] = sres * wt;
    } else {
        // -------- pairs path + KLD slice -----------------------------------------
        int pb = bid - HEAVY_BLOCKS;
        float term = 0.0f, psum = 0.0f;
        int base = pb * 1024;
        #pragma unroll
        for (int r = 0; r < 4; r++) {
            int p = base + r * 256 + tid;
            int ai = ii[p], bi = jj[p];
            float2 ma = ((const float2*)mu)[ai];
            float2 la = ((const float2*)lv)[ai];
            float2 ea = ((const float2*)epsi)[p];
            float2 mb = ((const float2*)mu)[bi];
            float2 lb = ((const float2*)lv)[bi];
            float2 eb = ((const float2*)epsj)[p];
            float xax = fmaf(ea.x, __expf(0.5f * la.x), ma.x);
            float xay = fmaf(ea.y, __expf(0.5f * la.y), ma.y);
            float xbx = fmaf(eb.x, __expf(0.5f * lb.x), mb.x);
            float xby = fmaf(eb.y, __expf(0.5f * lb.y), mb.y);
            float da = xax - xbx, db = xay - xby;
            float d2 = fmaf(da, da, db * db);
            float pv = pij[p];
            // pij*(log pij - log qij) = pij*(log pij + log(1+d2)) + pij*log(part)
            term += pv * (logf(pv) + log1pf(d2));
            psum += pv;
        }
        // KLD slice: 256 points per pair-block (64 * 256 = 16384)
        float kld;
        {
            int idx = pb * 256 + tid;
            float2 m = ((const float2*)mu)[idx];
            float2 l = ((const float2*)lv)[idx];
            kld = (1.0f + l.x - m.x * m.x - __expf(l.x))
                + (1.0f + l.y - m.y * m.y - __expf(l.y));
        }
        float s0 = block_reduce(term, sred);
        __syncthreads();
        float s1 = block_reduce(psum, sred1);
        __syncthreads();
        float s2 = block_reduce(kld, sred);
        if (tid == 0) {
            g_pair_p[pb] = s0;
            g_pij_p[pb]  = s1;
            g_kld_p[pb]  = s2;
        }
    }

    // -------- fused final: last CTA reduces everything ----------------------------
    __threadfence();
    if (tid == 0) s_last = atomicAdd(&g_ticket, 1u);
    __syncthreads();
    if (s_last == NBLOCKS - 1) {
        __threadfence();
        double part = 0.0, kld = 0.0, pair = 0.0, pijs = 0.0;
        for (int t = tid; t < HEAVY_BLOCKS; t += 256) part += (double)g_part_p[t];
        if (tid < PAIR_BLOCKS) {
            kld  = (double)g_kld_p[tid];
            pair = (double)g_pair_p[tid];
            pijs = (double)g_pij_p[tid];
        }
        double vals[4] = {part, kld, pair, pijs};
        double res[4];
        #pragma unroll
        for (int k = 0; k < 4; k++) {
            sdd[tid] = vals[k];
            __syncthreads();
            for (int o = 128; o > 0; o >>= 1) {
                if (tid < o) sdd[tid] += sdd[tid + o];
                __syncthreads();
            }
            res[k] = sdd[0];
            __syncthreads();
        }
        if (tid == 0) {
            double partv = res[0] - (double)N_POINTS;   // remove diagonal
            double loss = res[2] + res[3] * log(partv) + 1e-7 * (-0.5 * res[1]);
            out[0] = (float)loss;
            g_ticket = 0;   // reset for next graph replay
        }
    }
}

// -----------------------------------------------------------------------------
extern "C" void kernel_launch(void* const* d_in, const int* in_sizes, int n_in,
                              void* d_out, int out_size) {
    const float* pij      = (const float*)d_in[0];
    const int*   i_idx    = (const int*)  d_in[1];
    const int*   j_idx    = (const int*)  d_in[2];
    const float* mu_w     = (const float*)d_in[3];
    const float* lv_w     = (const float*)d_in[4];
    const float* eps_full = (const float*)d_in[5];
    const float* eps_i    = (const float*)d_in[6];
    const float* eps_j    = (const float*)d_in[7];
    float* out = (float*)d_out;

    k_main<<<NBLOCKS, 256>>>(pij, i_idx, j_idx, mu_w, lv_w,
                             eps_full, eps_i, eps_j, out);
}